// round 5
// baseline (speedup 1.0000x reference)
#include <cuda_runtime.h>
#include <math.h>

#define LSEQ 4096
#define DD   192
#define BB   2
#define TOT  (BB*LSEQ*DD)
#define LOG2E 1.4426950408889634f

// ---------------- scratch ----------------
__device__ __align__(16) float2 g_BC[TOT];   // [b][l][n] -> (B, C)
__device__ __align__(16) float2 g_dd[TOT];   // [b][d][l] -> (delta, delta*u)
__device__ __align__(16) float  g_uT[TOT];   // [b][d][l]

// ---------------- helpers ----------------
__device__ __forceinline__ float ex2f(float x) {
    float y;
    asm("ex2.approx.ftz.f32 %0, %1;" : "=f"(y) : "f"(x));
    return y;
}
__device__ __forceinline__ float softplus_f(float x) {
    if (x > 20.0f) return x;
    return log1pf(expf(x));
}
__device__ __forceinline__ void cp16(float* smem_dst, const float* gmem_src) {
    unsigned s = (unsigned)__cvta_generic_to_shared(smem_dst);
    asm volatile("cp.async.cg.shared.global [%0], [%1], 16;\n" :: "r"(s), "l"(gmem_src));
}
__device__ __forceinline__ void cp_commit() { asm volatile("cp.async.commit_group;\n" ::: "memory"); }
__device__ __forceinline__ void cp_wait0()  { asm volatile("cp.async.wait_group 0;\n" ::: "memory"); }

// ---------------- K1a: fused tokenize + B&C projections (interleaved output) ----------------
__global__ void projBC_kernel(const float* __restrict__ x,
                              const float* __restrict__ W_B, const float* __restrict__ b_B,
                              const float* __restrict__ W_C, const float* __restrict__ b_C) {
    __shared__ __align__(16) float As[16][128];
    __shared__ __align__(16) float Bs[16][64];
    __shared__ __align__(16) float Cs[16][64];

    int tid = threadIdx.x;
    int tx = tid & 15;
    int ty = tid >> 4;
    int m0 = blockIdx.x * 128;
    int jw0 = blockIdx.y * 64;

    float accB[8][4], accC[8][4];
#pragma unroll
    for (int i = 0; i < 8; i++)
#pragma unroll
        for (int j = 0; j < 4; j++) { accB[i][j] = 0.0f; accC[i][j] = 0.0f; }

    for (int kt = 0; kt < 12; kt++) {
        int k0 = kt * 16;
#pragma unroll
        for (int r = 0; r < 2; r++) {
            int idx  = tid + r * 256;
            int mrow = idx >> 2;
            int kq   = idx & 3;
            int m = m0 + mrow;
            int b = m >> 12;
            int l = m & 4095;
            int ih = l >> 6;
            int iw = l & 63;
            int c  = (k0 >> 2) + kq;
            const float* xb = x + (((b * 48 + c) * 128 + ih * 2) * 128 + iw * 2);
            float2 v01 = *(const float2*)xb;
            float2 v23 = *(const float2*)(xb + 128);
            As[kq * 4 + 0][mrow] = v01.x;
            As[kq * 4 + 1][mrow] = v01.y;
            As[kq * 4 + 2][mrow] = v23.x;
            As[kq * 4 + 3][mrow] = v23.y;
        }
        {
            int jrow = tid >> 2;
            int kq   = tid & 3;
            float4 vb = *(const float4*)&W_B[(jw0 + jrow) * 192 + k0 + kq * 4];
            float4 vc = *(const float4*)&W_C[(jw0 + jrow) * 192 + k0 + kq * 4];
            Bs[kq * 4 + 0][jrow] = vb.x; Bs[kq * 4 + 1][jrow] = vb.y;
            Bs[kq * 4 + 2][jrow] = vb.z; Bs[kq * 4 + 3][jrow] = vb.w;
            Cs[kq * 4 + 0][jrow] = vc.x; Cs[kq * 4 + 1][jrow] = vc.y;
            Cs[kq * 4 + 2][jrow] = vc.z; Cs[kq * 4 + 3][jrow] = vc.w;
        }
        __syncthreads();
#pragma unroll
        for (int kk = 0; kk < 16; kk++) {
            float4 a0 = *(const float4*)&As[kk][ty * 8];
            float4 a1 = *(const float4*)&As[kk][ty * 8 + 4];
            float4 bv = *(const float4*)&Bs[kk][tx * 4];
            float4 cv = *(const float4*)&Cs[kk][tx * 4];
            float a[8] = {a0.x, a0.y, a0.z, a0.w, a1.x, a1.y, a1.z, a1.w};
            float bb[4] = {bv.x, bv.y, bv.z, bv.w};
            float cc[4] = {cv.x, cv.y, cv.z, cv.w};
#pragma unroll
            for (int i = 0; i < 8; i++)
#pragma unroll
                for (int j = 0; j < 4; j++) {
                    accB[i][j] = fmaf(a[i], bb[j], accB[i][j]);
                    accC[i][j] = fmaf(a[i], cc[j], accC[i][j]);
                }
        }
        __syncthreads();
    }

    int ncol = jw0 + tx * 4;
    float4 bB4 = *(const float4*)&b_B[ncol];
    float4 bC4 = *(const float4*)&b_C[ncol];
#pragma unroll
    for (int i = 0; i < 8; i++) {
        int m = m0 + ty * 8 + i;
        float4 o01, o23;
        o01.x = accB[i][0] + bB4.x; o01.y = accC[i][0] + bC4.x;
        o01.z = accB[i][1] + bB4.y; o01.w = accC[i][1] + bC4.y;
        o23.x = accB[i][2] + bB4.z; o23.y = accC[i][2] + bC4.z;
        o23.z = accB[i][3] + bB4.w; o23.w = accC[i][3] + bC4.w;
        *(float4*)&g_BC[m * 192 + ncol]     = o01;
        *(float4*)&g_BC[m * 192 + ncol + 2] = o23;
    }
}

// ---------------- K1b: fused tokenize + dt projection ----------------
__global__ void projDT_kernel(const float* __restrict__ x,
                              const float* __restrict__ W_dt, const float* __restrict__ b_dt) {
    __shared__ __align__(16) float As[16][128];
    __shared__ __align__(16) float Bs[16][64];

    int tid = threadIdx.x;
    int tx = tid & 15;
    int ty = tid >> 4;
    int m0 = blockIdx.x * 128;
    int jw0 = blockIdx.y * 64;

    float acc[8][4];
#pragma unroll
    for (int i = 0; i < 8; i++)
#pragma unroll
        for (int j = 0; j < 4; j++) acc[i][j] = 0.0f;

    for (int kt = 0; kt < 12; kt++) {
        int k0 = kt * 16;
#pragma unroll
        for (int r = 0; r < 2; r++) {
            int idx  = tid + r * 256;
            int mrow = idx >> 2;
            int kq   = idx & 3;
            int m = m0 + mrow;
            int b = m >> 12;
            int l = m & 4095;
            int ih = l >> 6;
            int iw = l & 63;
            int c  = (k0 >> 2) + kq;
            const float* xb = x + (((b * 48 + c) * 128 + ih * 2) * 128 + iw * 2);
            float2 v01 = *(const float2*)xb;
            float2 v23 = *(const float2*)(xb + 128);
            As[kq * 4 + 0][mrow] = v01.x;
            As[kq * 4 + 1][mrow] = v01.y;
            As[kq * 4 + 2][mrow] = v23.x;
            As[kq * 4 + 3][mrow] = v23.y;
        }
        {
            int jrow = tid >> 2;
            int kq   = tid & 3;
            float4 v = *(const float4*)&W_dt[(jw0 + jrow) * 192 + k0 + kq * 4];
            Bs[kq * 4 + 0][jrow] = v.x; Bs[kq * 4 + 1][jrow] = v.y;
            Bs[kq * 4 + 2][jrow] = v.z; Bs[kq * 4 + 3][jrow] = v.w;
        }
        __syncthreads();
#pragma unroll
        for (int kk = 0; kk < 16; kk++) {
            float4 a0 = *(const float4*)&As[kk][ty * 8];
            float4 a1 = *(const float4*)&As[kk][ty * 8 + 4];
            float4 bv = *(const float4*)&Bs[kk][tx * 4];
            float a[8] = {a0.x, a0.y, a0.z, a0.w, a1.x, a1.y, a1.z, a1.w};
            float bb[4] = {bv.x, bv.y, bv.z, bv.w};
#pragma unroll
            for (int i = 0; i < 8; i++)
#pragma unroll
                for (int j = 0; j < 4; j++) acc[i][j] = fmaf(a[i], bb[j], acc[i][j]);
        }
        __syncthreads();
    }

    int ncol = jw0 + tx * 4;
    float bd[4];
#pragma unroll
    for (int j = 0; j < 4; j++) bd[j] = b_dt[ncol + j];
    int c2 = ncol >> 2;
#pragma unroll
    for (int i = 0; i < 8; i++) {
        int m = m0 + ty * 8 + i;
        int b = m >> 12;
        int l = m & 4095;
        int ih = l >> 6;
        int iw = l & 63;
        const float* xb = x + (((b * 48 + c2) * 128 + ih * 2) * 128 + iw * 2);
        float uvals[4];
        uvals[0] = xb[0];
        uvals[1] = xb[1];
        uvals[2] = xb[128];
        uvals[3] = xb[129];
#pragma unroll
        for (int j = 0; j < 4; j++) {
            int dfeat = ncol + j;
            float lin = acc[i][j] + bd[j];
            float dt  = softplus_f(lin);
            float del = softplus_f(dt + bd[j]);
            float u   = uvals[j];
            int o = (b * 192 + dfeat) * LSEQ + l;
            g_dd[o] = make_float2(del, del * u);
            g_uT[o] = u;
        }
    }
}

// ---------------- K2: selective scan ----------------
// 96 blocks x 384 threads (12 warps, 3/SMSP).
// warp w: dg = w&1 (d-pair), g = w>>1 (state group); lane owns state n = 32g+lane for 2 d's.
#define CH   32
#define PROW 104

__global__ void __launch_bounds__(384, 1)
scan_kernel(const float* __restrict__ A_log, const float* __restrict__ Dp,
            float* __restrict__ out) {
    extern __shared__ __align__(16) float S[];
    // floats: BC[2][CH*192*2]=24576 | P[128][PROW]=13312 | PS[384] | DD[2][2][CH] f4 =512 | U[2][128]=256 | Dp[4]
    float*  BCf  = S;
    float*  P    = S + 24576;
    float*  PS   = P + 13312;
    float4* DDq  = (float4*)(PS + 384);
    float*  Usm  = (float*)(DDq + 128);
    float*  Dpsm = Usm + 256;

    int tid  = threadIdx.x;
    int w    = tid >> 5;
    int lane = tid & 31;
    int dg = w & 1;
    int g  = w >> 1;
    int b = blockIdx.x / 48;
    int dbase = (blockIdx.x % 48) * 4;
    int d0 = dbase + 2 * dg;
    int d1 = d0 + 1;

    float A20 = -expf(A_log[d0 * 192 + g * 32 + lane]) * LOG2E;
    float A21 = -expf(A_log[d1 * 192 + g * 32 + lane]) * LOG2E;
    float h0 = 0.0f, h1 = 0.0f;
    if (tid < 4) Dpsm[tid] = Dp[dbase + tid];
    const float SILU1 = 0.73105857863000489f;

    const float*  BCsrc = (const float*)(g_BC + b * LSEQ * 192);
    const float2* dd0p  = g_dd + (b * 192 + d0) * LSEQ;
    const float2* dd1p  = g_dd + (b * 192 + d1) * LSEQ;

    // prologue: chunk 0
    {
#pragma unroll
        for (int q = 0; q < 8; q++) {
            int off = (tid + q * 384) * 4;
            cp16(BCf + off, BCsrc + off);
        }
        if (tid < 32) {
            int dl = tid >> 3, q = tid & 7;
            const float* usrc = g_uT + (b * 192 + dbase + dl) * LSEQ;
            cp16(Usm + dl * 32 + q * 4, usrc + q * 4);
        }
        cp_commit();
        if (w < 2) {
            float2 p0 = dd0p[lane];
            float2 p1 = dd1p[lane];
            DDq[dg * 32 + lane] = make_float4(p0.x, p0.y, p1.x, p1.y);
        }
        cp_wait0();
    }
    __syncthreads();

    const int NCHUNK = LSEQ / CH;
    for (int c = 0; c < NCHUNK; c++) {
        int l0  = c * CH;
        int buf = c & 1;

        float2 p0n, p1n;
        if (c + 1 < NCHUNK) {
            const float* bsrc = BCsrc + (l0 + CH) * 384;
            float* bdst = BCf + (buf ^ 1) * 12288;
#pragma unroll
            for (int q = 0; q < 8; q++) {
                int off = (tid + q * 384) * 4;
                cp16(bdst + off, bsrc + off);
            }
            if (tid < 32) {
                int dl = tid >> 3, q = tid & 7;
                const float* usrc = g_uT + (b * 192 + dbase + dl) * LSEQ + l0 + CH;
                cp16(Usm + (buf ^ 1) * 128 + dl * 32 + q * 4, usrc + q * 4);
            }
            cp_commit();
            if (w < 2) {
                p0n = dd0p[l0 + CH + lane];
                p1n = dd1p[l0 + CH + lane];
            }
        }

        // ---- compute 32 steps ----
        {
            const float2* bc  = (const float2*)(BCf + buf * 12288) + g * 32 + lane;
            const float4* DDc = DDq + buf * 64 + dg * 32;
            float* P0 = P + (2 * dg) * 32 * PROW + g * 16 + lane;
            float* P1 = P0 + 32 * PROW;
#pragma unroll 4
            for (int s = 0; s < CH; s++) {
                float4 dd = DDc[s];
                float2 v  = bc[s * 192];
                float e0 = ex2f(dd.x * A20);
                float e1 = ex2f(dd.z * A21);
                h0 = fmaf(e0, h0, dd.y * v.x);
                h1 = fmaf(e1, h1, dd.w * v.x);
                float a0 = h0 * v.y;
                float a1 = h1 * v.y;
                a0 += __shfl_xor_sync(0xffffffffu, a0, 16);
                a1 += __shfl_xor_sync(0xffffffffu, a1, 16);
                if (lane < 16) {
                    P0[s * PROW] = a0;
                    P1[s * PROW] = a1;
                }
            }
        }
        __syncthreads();

        // ---- reduce stage 1: 384 threads, row = tid/3 (d_local*32+s), segment = tid%3 ----
        {
            int row = tid / 3;
            int seg = tid - row * 3;
            const float* Pr = P + row * PROW + seg * 32;
            float4 q0 = *(const float4*)&Pr[0];
            float4 q1 = *(const float4*)&Pr[4];
            float4 q2 = *(const float4*)&Pr[8];
            float4 q3 = *(const float4*)&Pr[12];
            float4 q4 = *(const float4*)&Pr[16];
            float4 q5 = *(const float4*)&Pr[20];
            float4 q6 = *(const float4*)&Pr[24];
            float4 q7 = *(const float4*)&Pr[28];
            float s0 = (q0.x + q0.y) + (q0.z + q0.w);
            float s1 = (q1.x + q1.y) + (q1.z + q1.w);
            float s2 = (q2.x + q2.y) + (q2.z + q2.w);
            float s3 = (q3.x + q3.y) + (q3.z + q3.w);
            float s4 = (q4.x + q4.y) + (q4.z + q4.w);
            float s5 = (q5.x + q5.y) + (q5.z + q5.w);
            float s6 = (q6.x + q6.y) + (q6.z + q6.w);
            float s7 = (q7.x + q7.y) + (q7.z + q7.w);
            PS[tid] = ((s0 + s1) + (s2 + s3)) + ((s4 + s5) + (s6 + s7));
        }
        __syncthreads();

        // ---- reduce stage 2 + epilogue: 128 threads ----
        if (tid < 128) {
            float sum = PS[tid * 3] + PS[tid * 3 + 1] + PS[tid * 3 + 2];
            int dl = tid >> 5;
            int s  = tid & 31;
            float u   = Usm[buf * 128 + tid];
            float val = (sum + Dpsm[dl] * u) * SILU1;

            int d = dbase + dl;
            int l = l0 + s;
            int flat = d * LSEQ + l;
            int i1   = flat / 12288;
            int rem  = flat - i1 * 12288;
            int i2   = rem / 192;
            int r2   = rem - i2 * 192;
            int i3   = r2 >> 2;
            int i4   = (r2 >> 1) & 1;
            int i5   = r2 & 1;
            out[((b * 48 + i3) * 128 + i1 * 2 + i4) * 128 + i2 * 2 + i5] = val;
        }

        if (c + 1 < NCHUNK && w < 2) {
            DDq[(buf ^ 1) * 64 + dg * 32 + lane] = make_float4(p0n.x, p0n.y, p1n.x, p1n.y);
        }
        cp_wait0();
        __syncthreads();
    }
}

// ---------------- launch ----------------
extern "C" void kernel_launch(void* const* d_in, const int* in_sizes, int n_in,
                              void* d_out, int out_size) {
    (void)in_sizes; (void)n_in; (void)out_size;
    const float* x     = (const float*)d_in[0];
    const float* A_log = (const float*)d_in[1];
    const float* Dp    = (const float*)d_in[2];
    const float* W_B   = (const float*)d_in[3];
    const float* b_B   = (const float*)d_in[4];
    const float* W_C   = (const float*)d_in[5];
    const float* b_C   = (const float*)d_in[6];
    const float* W_dt  = (const float*)d_in[7];
    const float* b_dt  = (const float*)d_in[8];
    float* out = (float*)d_out;

    // smem floats: 24576 + 13312 + 384 + 512 + 256 + 4
    int smem = (24576 + 13312 + 384 + 512 + 256 + 4) * (int)sizeof(float);
    static int attr_set = 0;
    if (!attr_set) {
        cudaFuncSetAttribute(scan_kernel, cudaFuncAttributeMaxDynamicSharedMemorySize, smem);
        attr_set = 1;
    }

    dim3 gbc(64, 3);
    projBC_kernel<<<gbc, 256>>>(x, W_B, b_B, W_C, b_C);
    dim3 gdt(64, 3);
    projDT_kernel<<<gdt, 256>>>(x, W_dt, b_dt);
    scan_kernel<<<96, 384, smem>>>(A_log, Dp, out);
}

// round 6
// speedup vs baseline: 1.3388x; 1.3388x over previous
#include <cuda_runtime.h>
#include <math.h>

#define LSEQ 4096
#define DD   192
#define BB   2
#define TOT  (BB*LSEQ*DD)
#define LOG2E 1.4426950408889634f

// ---------------- scratch ----------------
__device__ __align__(16) float2 g_BC[TOT];   // [b][l][n] -> (B, C)
__device__ __align__(16) float2 g_dd[TOT];   // [b][d][l] -> (delta, delta*u)
__device__ __align__(16) float  g_uT[TOT];   // [b][d][l]

// ---------------- helpers ----------------
__device__ __forceinline__ float ex2f(float x) {
    float y;
    asm("ex2.approx.ftz.f32 %0, %1;" : "=f"(y) : "f"(x));
    return y;
}
__device__ __forceinline__ float softplus_f(float x) {
    if (x > 20.0f) return x;
    return log1pf(expf(x));
}
__device__ __forceinline__ void cp16(float* smem_dst, const float* gmem_src) {
    unsigned s = (unsigned)__cvta_generic_to_shared(smem_dst);
    asm volatile("cp.async.cg.shared.global [%0], [%1], 16;\n" :: "r"(s), "l"(gmem_src));
}
__device__ __forceinline__ void cp_commit() { asm volatile("cp.async.commit_group;\n" ::: "memory"); }
__device__ __forceinline__ void cp_wait0()  { asm volatile("cp.async.wait_group 0;\n" ::: "memory"); }

// ---------------- K1a: fused tokenize + B&C projections (interleaved (B,C) output) ----------------
__global__ void projBC_kernel(const float* __restrict__ x,
                              const float* __restrict__ W_B, const float* __restrict__ b_B,
                              const float* __restrict__ W_C, const float* __restrict__ b_C) {
    __shared__ __align__(16) float As[16][128];
    __shared__ __align__(16) float Bs[16][64];
    __shared__ __align__(16) float Cs[16][64];

    int tid = threadIdx.x;
    int tx = tid & 15;
    int ty = tid >> 4;
    int m0 = blockIdx.x * 128;
    int jw0 = blockIdx.y * 64;

    float accB[8][4], accC[8][4];
#pragma unroll
    for (int i = 0; i < 8; i++)
#pragma unroll
        for (int j = 0; j < 4; j++) { accB[i][j] = 0.0f; accC[i][j] = 0.0f; }

    for (int kt = 0; kt < 12; kt++) {
        int k0 = kt * 16;
#pragma unroll
        for (int r = 0; r < 2; r++) {
            int idx  = tid + r * 256;
            int mrow = idx >> 2;
            int kq   = idx & 3;
            int m = m0 + mrow;
            int b = m >> 12;
            int l = m & 4095;
            int ih = l >> 6;
            int iw = l & 63;
            int c  = (k0 >> 2) + kq;
            const float* xb = x + (((b * 48 + c) * 128 + ih * 2) * 128 + iw * 2);
            float2 v01 = *(const float2*)xb;
            float2 v23 = *(const float2*)(xb + 128);
            As[kq * 4 + 0][mrow] = v01.x;
            As[kq * 4 + 1][mrow] = v01.y;
            As[kq * 4 + 2][mrow] = v23.x;
            As[kq * 4 + 3][mrow] = v23.y;
        }
        {
            int jrow = tid >> 2;
            int kq   = tid & 3;
            float4 vb = *(const float4*)&W_B[(jw0 + jrow) * 192 + k0 + kq * 4];
            float4 vc = *(const float4*)&W_C[(jw0 + jrow) * 192 + k0 + kq * 4];
            Bs[kq * 4 + 0][jrow] = vb.x; Bs[kq * 4 + 1][jrow] = vb.y;
            Bs[kq * 4 + 2][jrow] = vb.z; Bs[kq * 4 + 3][jrow] = vb.w;
            Cs[kq * 4 + 0][jrow] = vc.x; Cs[kq * 4 + 1][jrow] = vc.y;
            Cs[kq * 4 + 2][jrow] = vc.z; Cs[kq * 4 + 3][jrow] = vc.w;
        }
        __syncthreads();
#pragma unroll
        for (int kk = 0; kk < 16; kk++) {
            float4 a0 = *(const float4*)&As[kk][ty * 8];
            float4 a1 = *(const float4*)&As[kk][ty * 8 + 4];
            float4 bv = *(const float4*)&Bs[kk][tx * 4];
            float4 cv = *(const float4*)&Cs[kk][tx * 4];
            float a[8] = {a0.x, a0.y, a0.z, a0.w, a1.x, a1.y, a1.z, a1.w};
            float bb[4] = {bv.x, bv.y, bv.z, bv.w};
            float cc[4] = {cv.x, cv.y, cv.z, cv.w};
#pragma unroll
            for (int i = 0; i < 8; i++)
#pragma unroll
                for (int j = 0; j < 4; j++) {
                    accB[i][j] = fmaf(a[i], bb[j], accB[i][j]);
                    accC[i][j] = fmaf(a[i], cc[j], accC[i][j]);
                }
        }
        __syncthreads();
    }

    int ncol = jw0 + tx * 4;
    float4 bB4 = *(const float4*)&b_B[ncol];
    float4 bC4 = *(const float4*)&b_C[ncol];
#pragma unroll
    for (int i = 0; i < 8; i++) {
        int m = m0 + ty * 8 + i;
        float4 o01, o23;
        o01.x = accB[i][0] + bB4.x; o01.y = accC[i][0] + bC4.x;
        o01.z = accB[i][1] + bB4.y; o01.w = accC[i][1] + bC4.y;
        o23.x = accB[i][2] + bB4.z; o23.y = accC[i][2] + bC4.z;
        o23.z = accB[i][3] + bB4.w; o23.w = accC[i][3] + bC4.w;
        *(float4*)&g_BC[m * 192 + ncol]     = o01;
        *(float4*)&g_BC[m * 192 + ncol + 2] = o23;
    }
}

// ---------------- K1b: fused tokenize + dt projection ----------------
__global__ void projDT_kernel(const float* __restrict__ x,
                              const float* __restrict__ W_dt, const float* __restrict__ b_dt) {
    __shared__ __align__(16) float As[16][128];
    __shared__ __align__(16) float Bs[16][64];

    int tid = threadIdx.x;
    int tx = tid & 15;
    int ty = tid >> 4;
    int m0 = blockIdx.x * 128;
    int jw0 = blockIdx.y * 64;

    float acc[8][4];
#pragma unroll
    for (int i = 0; i < 8; i++)
#pragma unroll
        for (int j = 0; j < 4; j++) acc[i][j] = 0.0f;

    for (int kt = 0; kt < 12; kt++) {
        int k0 = kt * 16;
#pragma unroll
        for (int r = 0; r < 2; r++) {
            int idx  = tid + r * 256;
            int mrow = idx >> 2;
            int kq   = idx & 3;
            int m = m0 + mrow;
            int b = m >> 12;
            int l = m & 4095;
            int ih = l >> 6;
            int iw = l & 63;
            int c  = (k0 >> 2) + kq;
            const float* xb = x + (((b * 48 + c) * 128 + ih * 2) * 128 + iw * 2);
            float2 v01 = *(const float2*)xb;
            float2 v23 = *(const float2*)(xb + 128);
            As[kq * 4 + 0][mrow] = v01.x;
            As[kq * 4 + 1][mrow] = v01.y;
            As[kq * 4 + 2][mrow] = v23.x;
            As[kq * 4 + 3][mrow] = v23.y;
        }
        {
            int jrow = tid >> 2;
            int kq   = tid & 3;
            float4 v = *(const float4*)&W_dt[(jw0 + jrow) * 192 + k0 + kq * 4];
            Bs[kq * 4 + 0][jrow] = v.x; Bs[kq * 4 + 1][jrow] = v.y;
            Bs[kq * 4 + 2][jrow] = v.z; Bs[kq * 4 + 3][jrow] = v.w;
        }
        __syncthreads();
#pragma unroll
        for (int kk = 0; kk < 16; kk++) {
            float4 a0 = *(const float4*)&As[kk][ty * 8];
            float4 a1 = *(const float4*)&As[kk][ty * 8 + 4];
            float4 bv = *(const float4*)&Bs[kk][tx * 4];
            float a[8] = {a0.x, a0.y, a0.z, a0.w, a1.x, a1.y, a1.z, a1.w};
            float bb[4] = {bv.x, bv.y, bv.z, bv.w};
#pragma unroll
            for (int i = 0; i < 8; i++)
#pragma unroll
                for (int j = 0; j < 4; j++) acc[i][j] = fmaf(a[i], bb[j], acc[i][j]);
        }
        __syncthreads();
    }

    int ncol = jw0 + tx * 4;
    float bd[4];
#pragma unroll
    for (int j = 0; j < 4; j++) bd[j] = b_dt[ncol + j];
    int c2 = ncol >> 2;
#pragma unroll
    for (int i = 0; i < 8; i++) {
        int m = m0 + ty * 8 + i;
        int b = m >> 12;
        int l = m & 4095;
        int ih = l >> 6;
        int iw = l & 63;
        const float* xb = x + (((b * 48 + c2) * 128 + ih * 2) * 128 + iw * 2);
        float uvals[4];
        uvals[0] = xb[0];
        uvals[1] = xb[1];
        uvals[2] = xb[128];
        uvals[3] = xb[129];
#pragma unroll
        for (int j = 0; j < 4; j++) {
            int dfeat = ncol + j;
            float lin = acc[i][j] + bd[j];
            float dt  = softplus_f(lin);
            float del = softplus_f(dt + bd[j]);
            float u   = uvals[j];
            int o = (b * 192 + dfeat) * LSEQ + l;
            g_dd[o] = make_float2(del, del * u);
            g_uT[o] = u;
        }
    }
}

// ---------------- K2: selective scan ----------------
// 96 blocks x 384 threads (12 warps, 3/SMSP).
// warp w: d_local = w&3, g = w>>2 in {0,1,2}; lane owns state pair n = g*64 + 2*lane, +1.
// Per step: 1 LDS.128 (B0,C0,B1,C1), 1 LDS.64 bcast (del,du), 2 ex2, 6 fma, 1 STS.
// Partials: P[(d_local*32+s)*108 + g*36 + lane]  (stride 108 + seg 36 -> conflict-free reduce).
#define CH   32
#define PR   108

__global__ void __launch_bounds__(384, 1)
scan_kernel(const float* __restrict__ A_log, const float* __restrict__ Dp,
            float* __restrict__ out) {
    extern __shared__ __align__(16) float S[];
    float*  BCf  = S;                      // [2][CH*384] = 24576
    float*  P    = S + 24576;              // [128][PR] = 13824
    float2* DDsm = (float2*)(P + 13824);   // [2][4][CH] = 256 float2 = 512 f
    float*  Usm  = (float*)(DDsm + 256);   // [2][128] = 256
    float*  Dpsm = Usm + 256;              // [4]

    int tid  = threadIdx.x;
    int w    = tid >> 5;
    int lane = tid & 31;
    int dl   = w & 3;          // d_local
    int g    = w >> 2;         // state group 0..2
    int b = blockIdx.x / 48;
    int dbase = (blockIdx.x % 48) * 4;
    int d = dbase + dl;

    int n0 = g * 64 + 2 * lane;
    float A20 = -expf(A_log[d * 192 + n0])     * LOG2E;
    float A21 = -expf(A_log[d * 192 + n0 + 1]) * LOG2E;
    float h0 = 0.0f, h1 = 0.0f;
    if (tid < 4) Dpsm[tid] = Dp[dbase + tid];
    const float SILU1 = 0.73105857863000489f;

    const float*  BCsrc = (const float*)(g_BC + b * LSEQ * 192);
    const float2* ddsrc = g_dd + (b * 192 + d) * LSEQ;

    // prologue: chunk 0
    {
#pragma unroll
        for (int q = 0; q < 8; q++) {
            int off = (tid + q * 384) * 4;
            cp16(BCf + off, BCsrc + off);
        }
        if (tid < 32) {
            int du_ = tid >> 3, q = tid & 7;
            const float* usrc = g_uT + (b * 192 + dbase + du_) * LSEQ;
            cp16(Usm + du_ * 32 + q * 4, usrc + q * 4);
        }
        cp_commit();
        if (w >= 8) {   // warps 8..11 load DD chunk 0 for d_local = w-8
            int dd_l = w - 8;
            DDsm[dd_l * CH + lane] = g_dd[(b * 192 + dbase + dd_l) * LSEQ + lane];
        }
        cp_wait0();
    }
    __syncthreads();

    const int NCHUNK = LSEQ / CH;
    for (int c = 0; c < NCHUNK; c++) {
        int l0  = c * CH;
        int buf = c & 1;

        float2 ddn = make_float2(0.f, 0.f);
        if (c + 1 < NCHUNK) {
            const float* bsrc = BCsrc + (l0 + CH) * 384;
            float* bdst = BCf + (buf ^ 1) * 12288;
#pragma unroll
            for (int q = 0; q < 8; q++) {
                int off = (tid + q * 384) * 4;
                cp16(bdst + off, bsrc + off);
            }
            if (tid < 32) {
                int du_ = tid >> 3, q = tid & 7;
                const float* usrc = g_uT + (b * 192 + dbase + du_) * LSEQ + l0 + CH;
                cp16(Usm + (buf ^ 1) * 128 + du_ * 32 + q * 4, usrc + q * 4);
            }
            cp_commit();
            if (w >= 8) {
                int dd_l = w - 8;
                ddn = g_dd[(b * 192 + dbase + dd_l) * LSEQ + l0 + CH + lane];
            }
        }

        // ---- compute 32 steps ----
        {
            const float4* bcp = (const float4*)(BCf + buf * 12288) + g * 32 + lane;
            const float2* DDc = DDsm + buf * 128 + dl * CH;
            float* Pw = P + (dl * 32) * PR + g * 36 + lane;
#pragma unroll 4
            for (int s = 0; s < CH; s++) {
                float2 dd = DDc[s];
                float4 bc = bcp[s * 96];
                float e0 = ex2f(dd.x * A20);
                float e1 = ex2f(dd.x * A21);
                h0 = fmaf(e0, h0, dd.y * bc.x);
                h1 = fmaf(e1, h1, dd.y * bc.z);
                float acc = fmaf(h0, bc.y, h1 * bc.w);
                Pw[s * PR] = acc;
            }
        }
        __syncthreads();

        // ---- reduce + epilogue (warps 0-3); DD store next chunk (warps 8-11) ----
        if (tid < 128) {
            const float* Pr = P + tid * PR;
            float sum = 0.0f;
#pragma unroll
            for (int seg = 0; seg < 3; seg++) {
                const float* Ps = Pr + seg * 36;
                float4 q0 = *(const float4*)&Ps[0];
                float4 q1 = *(const float4*)&Ps[4];
                float4 q2 = *(const float4*)&Ps[8];
                float4 q3 = *(const float4*)&Ps[12];
                float4 q4 = *(const float4*)&Ps[16];
                float4 q5 = *(const float4*)&Ps[20];
                float4 q6 = *(const float4*)&Ps[24];
                float4 q7 = *(const float4*)&Ps[28];
                float s0 = (q0.x + q0.y) + (q0.z + q0.w);
                float s1 = (q1.x + q1.y) + (q1.z + q1.w);
                float s2 = (q2.x + q2.y) + (q2.z + q2.w);
                float s3 = (q3.x + q3.y) + (q3.z + q3.w);
                float s4 = (q4.x + q4.y) + (q4.z + q4.w);
                float s5 = (q5.x + q5.y) + (q5.z + q5.w);
                float s6 = (q6.x + q6.y) + (q6.z + q6.w);
                float s7 = (q7.x + q7.y) + (q7.z + q7.w);
                sum += ((s0 + s1) + (s2 + s3)) + ((s4 + s5) + (s6 + s7));
            }
            int rdl = tid >> 5;
            int s   = tid & 31;
            float u   = Usm[buf * 128 + tid];
            float val = (sum + Dpsm[rdl] * u) * SILU1;

            int dd_ = dbase + rdl;
            int l = l0 + s;
            int flat = dd_ * LSEQ + l;
            int i1   = flat / 12288;
            int rem  = flat - i1 * 12288;
            int i2   = rem / 192;
            int r2   = rem - i2 * 192;
            int i3   = r2 >> 2;
            int i4   = (r2 >> 1) & 1;
            int i5   = r2 & 1;
            out[((b * 48 + i3) * 128 + i1 * 2 + i4) * 128 + i2 * 2 + i5] = val;
        } else if (w >= 8 && c + 1 < NCHUNK) {
            int dd_l = w - 8;
            DDsm[(buf ^ 1) * 128 + dd_l * CH + lane] = ddn;
        }

        cp_wait0();
        __syncthreads();
    }
}

// ---------------- launch ----------------
extern "C" void kernel_launch(void* const* d_in, const int* in_sizes, int n_in,
                              void* d_out, int out_size) {
    (void)in_sizes; (void)n_in; (void)out_size;
    const float* x     = (const float*)d_in[0];
    const float* A_log = (const float*)d_in[1];
    const float* Dp    = (const float*)d_in[2];
    const float* W_B   = (const float*)d_in[3];
    const float* b_B   = (const float*)d_in[4];
    const float* W_C   = (const float*)d_in[5];
    const float* b_C   = (const float*)d_in[6];
    const float* W_dt  = (const float*)d_in[7];
    const float* b_dt  = (const float*)d_in[8];
    float* out = (float*)d_out;

    // smem floats: BC 24576 + P 13824 + DD 512 + U 256 + Dp 4
    int smem = (24576 + 13824 + 512 + 256 + 4) * (int)sizeof(float);
    static int attr_set = 0;
    if (!attr_set) {
        cudaFuncSetAttribute(scan_kernel, cudaFuncAttributeMaxDynamicSharedMemorySize, smem);
        attr_set = 1;
    }

    dim3 gbc(64, 3);
    projBC_kernel<<<gbc, 256>>>(x, W_B, b_B, W_C, b_C);
    dim3 gdt(64, 3);
    projDT_kernel<<<gdt, 256>>>(x, W_dt, b_dt);
    scan_kernel<<<96, 384, smem>>>(A_log, Dp, out);
}

// round 7
// speedup vs baseline: 1.3832x; 1.0332x over previous
#include <cuda_runtime.h>
#include <math.h>

#define LSEQ 4096
#define DD   192
#define BB   2
#define TOT  (BB*LSEQ*DD)
#define LOG2E 1.4426950408889634f

// ---------------- scratch ----------------
__device__ __align__(16) float2 g_BC[TOT];   // [b][l][n] -> (B, C)
__device__ __align__(16) float2 g_dd[TOT];   // [b][d][l] -> (delta, delta*u)
__device__ __align__(16) float  g_uT[TOT];   // [b][d][l]

// ---------------- helpers ----------------
__device__ __forceinline__ float ex2f(float x) {
    float y;
    asm("ex2.approx.ftz.f32 %0, %1;" : "=f"(y) : "f"(x));
    return y;
}
__device__ __forceinline__ float softplus_f(float x) {
    if (x > 20.0f) return x;
    return log1pf(expf(x));
}
__device__ __forceinline__ void cp16(float* smem_dst, const float* gmem_src) {
    unsigned s = (unsigned)__cvta_generic_to_shared(smem_dst);
    asm volatile("cp.async.cg.shared.global [%0], [%1], 16;\n" :: "r"(s), "l"(gmem_src));
}
__device__ __forceinline__ void cp_commit() { asm volatile("cp.async.commit_group;\n" ::: "memory"); }
__device__ __forceinline__ void cp_wait0()  { asm volatile("cp.async.wait_group 0;\n" ::: "memory"); }

// ---------------- K1a: fused tokenize + B&C projections ----------------
__global__ void projBC_kernel(const float* __restrict__ x,
                              const float* __restrict__ W_B, const float* __restrict__ b_B,
                              const float* __restrict__ W_C, const float* __restrict__ b_C) {
    __shared__ __align__(16) float As[16][128];
    __shared__ __align__(16) float Bs[16][64];
    __shared__ __align__(16) float Cs[16][64];

    int tid = threadIdx.x;
    int tx = tid & 15;
    int ty = tid >> 4;
    int m0 = blockIdx.x * 128;
    int jw0 = blockIdx.y * 64;

    float accB[8][4], accC[8][4];
#pragma unroll
    for (int i = 0; i < 8; i++)
#pragma unroll
        for (int j = 0; j < 4; j++) { accB[i][j] = 0.0f; accC[i][j] = 0.0f; }

    for (int kt = 0; kt < 12; kt++) {
        int k0 = kt * 16;
#pragma unroll
        for (int r = 0; r < 2; r++) {
            int idx  = tid + r * 256;
            int mrow = idx >> 2;
            int kq   = idx & 3;
            int m = m0 + mrow;
            int b = m >> 12;
            int l = m & 4095;
            int ih = l >> 6;
            int iw = l & 63;
            int c  = (k0 >> 2) + kq;
            const float* xb = x + (((b * 48 + c) * 128 + ih * 2) * 128 + iw * 2);
            float2 v01 = *(const float2*)xb;
            float2 v23 = *(const float2*)(xb + 128);
            As[kq * 4 + 0][mrow] = v01.x;
            As[kq * 4 + 1][mrow] = v01.y;
            As[kq * 4 + 2][mrow] = v23.x;
            As[kq * 4 + 3][mrow] = v23.y;
        }
        {
            int jrow = tid >> 2;
            int kq   = tid & 3;
            float4 vb = *(const float4*)&W_B[(jw0 + jrow) * 192 + k0 + kq * 4];
            float4 vc = *(const float4*)&W_C[(jw0 + jrow) * 192 + k0 + kq * 4];
            Bs[kq * 4 + 0][jrow] = vb.x; Bs[kq * 4 + 1][jrow] = vb.y;
            Bs[kq * 4 + 2][jrow] = vb.z; Bs[kq * 4 + 3][jrow] = vb.w;
            Cs[kq * 4 + 0][jrow] = vc.x; Cs[kq * 4 + 1][jrow] = vc.y;
            Cs[kq * 4 + 2][jrow] = vc.z; Cs[kq * 4 + 3][jrow] = vc.w;
        }
        __syncthreads();
#pragma unroll
        for (int kk = 0; kk < 16; kk++) {
            float4 a0 = *(const float4*)&As[kk][ty * 8];
            float4 a1 = *(const float4*)&As[kk][ty * 8 + 4];
            float4 bv = *(const float4*)&Bs[kk][tx * 4];
            float4 cv = *(const float4*)&Cs[kk][tx * 4];
            float a[8] = {a0.x, a0.y, a0.z, a0.w, a1.x, a1.y, a1.z, a1.w};
            float bb[4] = {bv.x, bv.y, bv.z, bv.w};
            float cc[4] = {cv.x, cv.y, cv.z, cv.w};
#pragma unroll
            for (int i = 0; i < 8; i++)
#pragma unroll
                for (int j = 0; j < 4; j++) {
                    accB[i][j] = fmaf(a[i], bb[j], accB[i][j]);
                    accC[i][j] = fmaf(a[i], cc[j], accC[i][j]);
                }
        }
        __syncthreads();
    }

    int ncol = jw0 + tx * 4;
    float4 bB4 = *(const float4*)&b_B[ncol];
    float4 bC4 = *(const float4*)&b_C[ncol];
#pragma unroll
    for (int i = 0; i < 8; i++) {
        int m = m0 + ty * 8 + i;
        float4 o01, o23;
        o01.x = accB[i][0] + bB4.x; o01.y = accC[i][0] + bC4.x;
        o01.z = accB[i][1] + bB4.y; o01.w = accC[i][1] + bC4.y;
        o23.x = accB[i][2] + bB4.z; o23.y = accC[i][2] + bC4.z;
        o23.z = accB[i][3] + bB4.w; o23.w = accC[i][3] + bC4.w;
        *(float4*)&g_BC[m * 192 + ncol]     = o01;
        *(float4*)&g_BC[m * 192 + ncol + 2] = o23;
    }
}

// ---------------- K1b: fused tokenize + dt projection ----------------
__global__ void projDT_kernel(const float* __restrict__ x,
                              const float* __restrict__ W_dt, const float* __restrict__ b_dt) {
    __shared__ __align__(16) float As[16][128];
    __shared__ __align__(16) float Bs[16][64];

    int tid = threadIdx.x;
    int tx = tid & 15;
    int ty = tid >> 4;
    int m0 = blockIdx.x * 128;
    int jw0 = blockIdx.y * 64;

    float acc[8][4];
#pragma unroll
    for (int i = 0; i < 8; i++)
#pragma unroll
        for (int j = 0; j < 4; j++) acc[i][j] = 0.0f;

    for (int kt = 0; kt < 12; kt++) {
        int k0 = kt * 16;
#pragma unroll
        for (int r = 0; r < 2; r++) {
            int idx  = tid + r * 256;
            int mrow = idx >> 2;
            int kq   = idx & 3;
            int m = m0 + mrow;
            int b = m >> 12;
            int l = m & 4095;
            int ih = l >> 6;
            int iw = l & 63;
            int c  = (k0 >> 2) + kq;
            const float* xb = x + (((b * 48 + c) * 128 + ih * 2) * 128 + iw * 2);
            float2 v01 = *(const float2*)xb;
            float2 v23 = *(const float2*)(xb + 128);
            As[kq * 4 + 0][mrow] = v01.x;
            As[kq * 4 + 1][mrow] = v01.y;
            As[kq * 4 + 2][mrow] = v23.x;
            As[kq * 4 + 3][mrow] = v23.y;
        }
        {
            int jrow = tid >> 2;
            int kq   = tid & 3;
            float4 v = *(const float4*)&W_dt[(jw0 + jrow) * 192 + k0 + kq * 4];
            Bs[kq * 4 + 0][jrow] = v.x; Bs[kq * 4 + 1][jrow] = v.y;
            Bs[kq * 4 + 2][jrow] = v.z; Bs[kq * 4 + 3][jrow] = v.w;
        }
        __syncthreads();
#pragma unroll
        for (int kk = 0; kk < 16; kk++) {
            float4 a0 = *(const float4*)&As[kk][ty * 8];
            float4 a1 = *(const float4*)&As[kk][ty * 8 + 4];
            float4 bv = *(const float4*)&Bs[kk][tx * 4];
            float a[8] = {a0.x, a0.y, a0.z, a0.w, a1.x, a1.y, a1.z, a1.w};
            float bb[4] = {bv.x, bv.y, bv.z, bv.w};
#pragma unroll
            for (int i = 0; i < 8; i++)
#pragma unroll
                for (int j = 0; j < 4; j++) acc[i][j] = fmaf(a[i], bb[j], acc[i][j]);
        }
        __syncthreads();
    }

    int ncol = jw0 + tx * 4;
    float bd[4];
#pragma unroll
    for (int j = 0; j < 4; j++) bd[j] = b_dt[ncol + j];
    int c2 = ncol >> 2;
#pragma unroll
    for (int i = 0; i < 8; i++) {
        int m = m0 + ty * 8 + i;
        int b = m >> 12;
        int l = m & 4095;
        int ih = l >> 6;
        int iw = l & 63;
        const float* xb = x + (((b * 48 + c2) * 128 + ih * 2) * 128 + iw * 2);
        float uvals[4];
        uvals[0] = xb[0];
        uvals[1] = xb[1];
        uvals[2] = xb[128];
        uvals[3] = xb[129];
#pragma unroll
        for (int j = 0; j < 4; j++) {
            int dfeat = ncol + j;
            float lin = acc[i][j] + bd[j];
            float dt  = softplus_f(lin);
            float del = softplus_f(dt + bd[j]);
            float u   = uvals[j];
            int o = (b * 192 + dfeat) * LSEQ + l;
            g_dd[o] = make_float2(del, del * u);
            g_uT[o] = u;
        }
    }
}

// ---------------- K2: selective scan ----------------
// 128 blocks x 288 threads (9 warps). Block covers 3 d's (b = blk/64, dbase = (blk%64)*3).
// warp w: dl = w/3, g = w%3; lane owns state pair n = g*64 + 2*lane for d = dbase+dl.
// Partials: P[(dl*32+s)*108 + g*36 + lane]  (27 mod 8 = 3 -> conflict-free reduce reads).
#define CH   32
#define PR   108

__global__ void __launch_bounds__(288, 1)
scan_kernel(const float* __restrict__ A_log, const float* __restrict__ Dp,
            float* __restrict__ out) {
    extern __shared__ __align__(16) float S[];
    float*  BCf  = S;                      // [2][CH*384] = 24576
    float*  P    = S + 24576;              // [96][PR] = 10368
    float2* DDsm = (float2*)(P + 10368);   // [2][3][CH] = 192 float2 = 384 f
    float*  Usm  = (float*)(DDsm + 192);   // [2][96] = 192
    float*  Dpsm = Usm + 192;              // [3]+pad

    int tid  = threadIdx.x;
    int w    = tid >> 5;
    int lane = tid & 31;
    int dl   = w / 3;          // d_local 0..2
    int g    = w - dl * 3;     // state group 0..2
    int b = blockIdx.x >> 6;
    int dbase = (blockIdx.x & 63) * 3;
    int d = dbase + dl;

    int n0 = g * 64 + 2 * lane;
    float A20 = -expf(A_log[d * 192 + n0])     * LOG2E;
    float A21 = -expf(A_log[d * 192 + n0 + 1]) * LOG2E;
    float h0 = 0.0f, h1 = 0.0f;
    if (tid < 3) Dpsm[tid] = Dp[dbase + tid];
    const float SILU1 = 0.73105857863000489f;

    const float* BCsrc = (const float*)(g_BC + b * LSEQ * 192);

    // prologue: chunk 0
    {
#pragma unroll
        for (int q = 0; q < 10; q++) {
            int off = (tid + q * 288) * 4;
            cp16(BCf + off, BCsrc + off);
        }
        if (tid < 192) {
            int off = (tid + 2880) * 4;
            cp16(BCf + off, BCsrc + off);
        }
        if (tid < 24) {
            int du_ = tid >> 3, q = tid & 7;
            const float* usrc = g_uT + (b * 192 + dbase + du_) * LSEQ;
            cp16(Usm + du_ * 32 + q * 4, usrc + q * 4);
        }
        cp_commit();
        if (w >= 6) {   // warps 6..8 load DD chunk 0 for d_local = w-6
            int dd_l = w - 6;
            DDsm[dd_l * CH + lane] = g_dd[(b * 192 + dbase + dd_l) * LSEQ + lane];
        }
        cp_wait0();
    }
    __syncthreads();

    const int NCHUNK = LSEQ / CH;
    for (int c = 0; c < NCHUNK; c++) {
        int l0  = c * CH;
        int buf = c & 1;

        float2 ddn = make_float2(0.f, 0.f);
        if (c + 1 < NCHUNK) {
            const float* bsrc = BCsrc + (l0 + CH) * 384;
            float* bdst = BCf + (buf ^ 1) * 12288;
#pragma unroll
            for (int q = 0; q < 10; q++) {
                int off = (tid + q * 288) * 4;
                cp16(bdst + off, bsrc + off);
            }
            if (tid < 192) {
                int off = (tid + 2880) * 4;
                cp16(bdst + off, bsrc + off);
            }
            if (tid < 24) {
                int du_ = tid >> 3, q = tid & 7;
                const float* usrc = g_uT + (b * 192 + dbase + du_) * LSEQ + l0 + CH;
                cp16(Usm + (buf ^ 1) * 96 + du_ * 32 + q * 4, usrc + q * 4);
            }
            cp_commit();
            if (w >= 6) {
                int dd_l = w - 6;
                ddn = g_dd[(b * 192 + dbase + dd_l) * LSEQ + l0 + CH + lane];
            }
        }

        // ---- compute 32 steps ----
        {
            const float4* bcp = (const float4*)(BCf + buf * 12288) + g * 32 + lane;
            const float2* DDc = DDsm + buf * 96 + dl * CH;
            float* Pw = P + (dl * 32) * PR + g * 36 + lane;
#pragma unroll 4
            for (int s = 0; s < CH; s++) {
                float2 dd = DDc[s];
                float4 bc = bcp[s * 96];
                float e0 = ex2f(dd.x * A20);
                float e1 = ex2f(dd.x * A21);
                h0 = fmaf(e0, h0, dd.y * bc.x);
                h1 = fmaf(e1, h1, dd.y * bc.z);
                float acc = fmaf(h0, bc.y, h1 * bc.w);
                Pw[s * PR] = acc;
            }
        }
        __syncthreads();

        // ---- reduce + epilogue (tid<96); DD store next chunk (warps 6-8) ----
        if (tid < 96) {
            const float* Pr = P + tid * PR;
            float sum = 0.0f;
#pragma unroll
            for (int seg = 0; seg < 3; seg++) {
                const float* Ps = Pr + seg * 36;
                float4 q0 = *(const float4*)&Ps[0];
                float4 q1 = *(const float4*)&Ps[4];
                float4 q2 = *(const float4*)&Ps[8];
                float4 q3 = *(const float4*)&Ps[12];
                float4 q4 = *(const float4*)&Ps[16];
                float4 q5 = *(const float4*)&Ps[20];
                float4 q6 = *(const float4*)&Ps[24];
                float4 q7 = *(const float4*)&Ps[28];
                float s0 = (q0.x + q0.y) + (q0.z + q0.w);
                float s1 = (q1.x + q1.y) + (q1.z + q1.w);
                float s2 = (q2.x + q2.y) + (q2.z + q2.w);
                float s3 = (q3.x + q3.y) + (q3.z + q3.w);
                float s4 = (q4.x + q4.y) + (q4.z + q4.w);
                float s5 = (q5.x + q5.y) + (q5.z + q5.w);
                float s6 = (q6.x + q6.y) + (q6.z + q6.w);
                float s7 = (q7.x + q7.y) + (q7.z + q7.w);
                sum += ((s0 + s1) + (s2 + s3)) + ((s4 + s5) + (s6 + s7));
            }
            int rdl = tid >> 5;
            int s   = tid & 31;
            float u   = Usm[buf * 96 + tid];
            float val = (sum + Dpsm[rdl] * u) * SILU1;

            int dd_ = dbase + rdl;
            int l = l0 + s;
            int flat = dd_ * LSEQ + l;
            int i1   = flat / 12288;
            int rem  = flat - i1 * 12288;
            int i2   = rem / 192;
            int r2   = rem - i2 * 192;
            int i3   = r2 >> 2;
            int i4   = (r2 >> 1) & 1;
            int i5   = r2 & 1;
            out[((b * 48 + i3) * 128 + i1 * 2 + i4) * 128 + i2 * 2 + i5] = val;
        } else if (w >= 6 && c + 1 < NCHUNK) {
            int dd_l = w - 6;
            DDsm[(buf ^ 1) * 96 + dd_l * CH + lane] = ddn;
        }

        cp_wait0();
        __syncthreads();
    }
}

// ---------------- launch ----------------
extern "C" void kernel_launch(void* const* d_in, const int* in_sizes, int n_in,
                              void* d_out, int out_size) {
    (void)in_sizes; (void)n_in; (void)out_size;
    const float* x     = (const float*)d_in[0];
    const float* A_log = (const float*)d_in[1];
    const float* Dp    = (const float*)d_in[2];
    const float* W_B   = (const float*)d_in[3];
    const float* b_B   = (const float*)d_in[4];
    const float* W_C   = (const float*)d_in[5];
    const float* b_C   = (const float*)d_in[6];
    const float* W_dt  = (const float*)d_in[7];
    const float* b_dt  = (const float*)d_in[8];
    float* out = (float*)d_out;

    // smem floats: BC 24576 + P 10368 + DD 384 + U 192 + Dp 4
    int smem = (24576 + 10368 + 384 + 192 + 4) * (int)sizeof(float);
    static int attr_set = 0;
    if (!attr_set) {
        cudaFuncSetAttribute(scan_kernel, cudaFuncAttributeMaxDynamicSharedMemorySize, smem);
        attr_set = 1;
    }

    dim3 gbc(64, 3);
    projBC_kernel<<<gbc, 256>>>(x, W_B, b_B, W_C, b_C);
    dim3 gdt(64, 3);
    projDT_kernel<<<gdt, 256>>>(x, W_dt, b_dt);
    scan_kernel<<<128, 288, smem>>>(A_log, Dp, out);
}